// round 13
// baseline (speedup 1.0000x reference)
#include <cuda_runtime.h>
#include <cuda_fp16.h>

#define N_NODES 50000
#define N_EDGES 800000
#define IN_F 64
#define OUT_F 64
#define ELL_W 64          // max supported degree (Poisson(16): P(>64) ~ 0)
#define BPT 4             // edge batch depth (chunk <= 1024 = 256*4)

// Device scratch (no allocations allowed; zero-initialized at load)
__device__ __half g_support_h[N_NODES * OUT_F];    // 6.4 MB fp16 support
__device__ int    g_deg[N_NODES];
__device__ int2   g_ell[N_NODES * ELL_W + 4];      // +4 pad for batched reads

// ---------------------------------------------------------------------------
// Kernel 1 (FUSED + PIPELINED): the build phase's atomic/load latency is
// hidden UNDER this block's own FFMA loop:
//   load edge rows -> stage smem -> issue atomics + col/val loads ->
//   FFMA loop (~1300 cyc) -> sup stores -> ell stores.
// ---------------------------------------------------------------------------
__global__ __launch_bounds__(256) void gemm_build_kernel(
    const float* __restrict__ x,
    const float* __restrict__ w,
    __half* __restrict__ suph,
    const int* __restrict__ edge_row,
    const int* __restrict__ edge_col,
    const float* __restrict__ edge_val,
    int* __restrict__ deg,
    int2* __restrict__ ell,
    int n_nodes, int n_edges) {
    __shared__ float sw[IN_F * OUT_F];        // w[k*64 + col]
    __shared__ float sx[64 * 65];             // x rows, padded stride 65

    int t  = threadIdx.x;
    int tx = t & 15;
    int ty = t >> 4;

    // ---- build phase A: edge-row loads in flight early ----
    int chunk = (n_edges + gridDim.x - 1) / gridDim.x;
    int cstart = blockIdx.x * chunk;
    int cend   = cstart + chunk;
    if (cend > n_edges) cend = n_edges;

    int  e[BPT], r[BPT];
    bool ok[BPT];
    #pragma unroll
    for (int i = 0; i < BPT; ++i) {
        e[i]  = cstart + i * 256 + t;
        ok[i] = (e[i] < cend);
        int ee = ok[i] ? e[i] : 0;
        r[i] = __ldg(edge_row + ee);
    }

    // ---- stage W and x (vectorized LDG) ----
    #pragma unroll
    for (int j = 0; j < 4; ++j) {
        int i4 = t + j * 256;                 // float4 index into w
        float4 wv4 = *reinterpret_cast<const float4*>(w + i4 * 4);
        *reinterpret_cast<float4*>(&sw[i4 * 4]) = wv4;
    }

    int base = blockIdx.x * 64;
    #pragma unroll
    for (int j = 0; j < 4; ++j) {
        int i4 = t + j * 256;                 // float4 index into x tile
        int rr = i4 >> 4;                     // row (16 float4 per row)
        int kk = (i4 & 15) * 4;               // col
        int node = base + rr;
        float4 xv4 = (node < n_nodes)
            ? *reinterpret_cast<const float4*>(x + (long long)node * IN_F + kk)
            : make_float4(0.f, 0.f, 0.f, 0.f);
        float* dst = &sx[rr * 65 + kk];
        dst[0] = xv4.x; dst[1] = xv4.y; dst[2] = xv4.z; dst[3] = xv4.w;
    }
    __syncthreads();

    // ---- build phase B: atomics + col/val loads (latency hidden below) ----
    int rank[BPT];
    #pragma unroll
    for (int i = 0; i < BPT; ++i)
        rank[i] = ok[i] ? atomicAdd(&deg[r[i]], 1) : ELL_W;

    int   c[BPT];
    float v[BPT];
    #pragma unroll
    for (int i = 0; i < BPT; ++i) {
        int ee = ok[i] ? e[i] : 0;
        c[i] = __ldg(edge_col + ee);
        v[i] = __ldg(edge_val + ee);
    }

    // ---- GEMM compute (covers the atomic/LDG latency above) ----
    float acc[4][4] = {};
    #pragma unroll
    for (int k = 0; k < IN_F; ++k) {
        float xv[4];
        #pragma unroll
        for (int rr = 0; rr < 4; ++rr) xv[rr] = sx[(ty * 4 + rr) * 65 + k];
        float4 wv = *reinterpret_cast<const float4*>(&sw[k * OUT_F + tx * 4]);
        #pragma unroll
        for (int rr = 0; rr < 4; ++rr) {
            acc[rr][0] = fmaf(xv[rr], wv.x, acc[rr][0]);
            acc[rr][1] = fmaf(xv[rr], wv.y, acc[rr][1]);
            acc[rr][2] = fmaf(xv[rr], wv.z, acc[rr][2]);
            acc[rr][3] = fmaf(xv[rr], wv.w, acc[rr][3]);
        }
    }

    #pragma unroll
    for (int rr = 0; rr < 4; ++rr) {
        int node = base + ty * 4 + rr;
        if (node < n_nodes) {
            __half2 h0 = __floats2half2_rn(acc[rr][0], acc[rr][1]);
            __half2 h1 = __floats2half2_rn(acc[rr][2], acc[rr][3]);
            uint2 packed = make_uint2(
                *reinterpret_cast<unsigned*>(&h0),
                *reinterpret_cast<unsigned*>(&h1));
            *reinterpret_cast<uint2*>(suph + (long long)node * OUT_F + tx * 4)
                = packed;
        }
    }

    // ---- build phase C: ELL stores (ranks have long since returned) ----
    #pragma unroll
    for (int i = 0; i < BPT; ++i) {
        if (ok[i] && rank[i] < ELL_W) {
            ell[(long long)r[i] * ELL_W + rank[i]] =
                make_int2(c[i], __float_as_int(v[i]));
        }
    }

    // Fallback (never executes for these sizes: chunk <= 1024)
    for (int ebase = cstart + 256 * BPT; ebase < cend; ebase += 256) {
        int ee = ebase + t;
        if (ee < cend) {
            int rr2 = __ldg(edge_row + ee);
            int rk = atomicAdd(&deg[rr2], 1);
            if (rk < ELL_W)
                ell[(long long)rr2 * ELL_W + rk] =
                    make_int2(__ldg(edge_col + ee),
                              __float_as_int(__ldg(edge_val + ee)));
        }
    }
}

// ---------------------------------------------------------------------------
// Kernel 2: accumulate, 8 lanes per row (lane owns 8 features = one uint4 of
// halves). fp32 accumulation, predicated batches of 4, no serial tail.
// ---------------------------------------------------------------------------
__global__ __launch_bounds__(256) void accumulate_kernel(
    const int* __restrict__ deg,
    const int2* __restrict__ ell,
    const __half* __restrict__ suph,
    const float* __restrict__ bias,
    float* __restrict__ out,
    int n_nodes) {
    int t = threadIdx.x;
    int g = blockIdx.x * 32 + (t >> 3);   // row (32 rows per block)
    int l = t & 7;                         // lane: features l*8 .. l*8+7
    if (g >= n_nodes) return;

    int d = deg[g];
    if (d > ELL_W) d = ELL_W;
    const int2* row = ell + (long long)g * ELL_W;

    float4 acc0 = *reinterpret_cast<const float4*>(bias + l * 8);
    float4 acc1 = *reinterpret_cast<const float4*>(bias + l * 8 + 4);

    for (int e = 0; e < d; e += 4) {
        int2 ev[4];
        #pragma unroll
        for (int i = 0; i < 4; ++i) ev[i] = __ldg(row + e + i);
        uint4 sh[4];
        #pragma unroll
        for (int i = 0; i < 4; ++i)
            sh[i] = *reinterpret_cast<const uint4*>(
                suph + (long long)ev[i].x * OUT_F + l * 8);
        #pragma unroll
        for (int i = 0; i < 4; ++i) {
            float v = (e + i < d) ? __int_as_float(ev[i].y) : 0.0f;
            float2 f0 = __half22float2(*reinterpret_cast<__half2*>(&sh[i].x));
            float2 f1 = __half22float2(*reinterpret_cast<__half2*>(&sh[i].y));
            float2 f2 = __half22float2(*reinterpret_cast<__half2*>(&sh[i].z));
            float2 f3 = __half22float2(*reinterpret_cast<__half2*>(&sh[i].w));
            acc0.x = fmaf(v, f0.x, acc0.x);
            acc0.y = fmaf(v, f0.y, acc0.y);
            acc0.z = fmaf(v, f1.x, acc0.z);
            acc0.w = fmaf(v, f1.y, acc0.w);
            acc1.x = fmaf(v, f2.x, acc1.x);
            acc1.y = fmaf(v, f2.y, acc1.y);
            acc1.z = fmaf(v, f3.x, acc1.z);
            acc1.w = fmaf(v, f3.y, acc1.w);
        }
    }

    float* o = out + (long long)g * OUT_F + l * 8;
    *reinterpret_cast<float4*>(o)     = acc0;
    *reinterpret_cast<float4*>(o + 4) = acc1;
}

// ---------------------------------------------------------------------------
// Launch: inputs in order  x, edge_row, edge_col, edge_val, weight, bias
// ---------------------------------------------------------------------------
extern "C" void kernel_launch(void* const* d_in, const int* in_sizes, int n_in,
                              void* d_out, int out_size) {
    const float* x        = (const float*)d_in[0];
    const int*   edge_row = (const int*)  d_in[1];
    const int*   edge_col = (const int*)  d_in[2];
    const float* edge_val = (const float*)d_in[3];
    const float* weight   = (const float*)d_in[4];
    const float* bias     = (const float*)d_in[5];
    float* out = (float*)d_out;

    int n_nodes = in_sizes[0] / IN_F;
    int n_edges = in_sizes[1];

    __half* suph;
    int* deg;
    int2* ell;
    cudaGetSymbolAddress((void**)&suph, g_support_h);
    cudaGetSymbolAddress((void**)&deg,  g_deg);
    cudaGetSymbolAddress((void**)&ell,  g_ell);

    // 0) zero deg (graph memset node)
    cudaMemsetAsync(deg, 0, n_nodes * sizeof(int));

    // 1) fused + pipelined GEMM/ELL build
    int blocks = (n_nodes + 63) / 64;
    gemm_build_kernel<<<blocks, 256>>>(x, weight, suph,
                                       edge_row, edge_col, edge_val,
                                       deg, ell, n_nodes, n_edges);

    // 2) accumulate (8 lanes per row)
    int ablocks = (n_nodes + 31) / 32;
    accumulate_kernel<<<ablocks, 256>>>(deg, ell, suph, bias, out, n_nodes);
}

// round 14
// speedup vs baseline: 1.2078x; 1.2078x over previous
#include <cuda_runtime.h>
#include <cuda_fp16.h>

#define N_NODES 50000
#define N_EDGES 800000
#define IN_F 64
#define OUT_F 64
#define ELL_W 64          // max supported degree (Poisson(16): P(>64) ~ 0)
#define BPT 4             // edge batch depth (chunk <= 1024 = 256*4)

// Device scratch (no allocations allowed; zero-initialized at load)
__device__ __half g_support_h[N_NODES * OUT_F];    // 6.4 MB fp16 support
__device__ int    g_deg[N_NODES];
__device__ int2   g_ell[N_NODES * ELL_W + 4];      // +4 pad for batched reads

// ---------------------------------------------------------------------------
// Kernel 1 (FUSED + PIPELINED): build-phase atomic/load latency hidden under
// this block's own FFMA loop:
//   edge-row loads -> stage smem (vectorized) -> atomics + col/val loads ->
//   FFMA loop (~1300 cyc) -> sup stores -> ell stores.
// ---------------------------------------------------------------------------
__global__ __launch_bounds__(256) void gemm_build_kernel(
    const float* __restrict__ x,
    const float* __restrict__ w,
    __half* __restrict__ suph,
    const int* __restrict__ edge_row,
    const int* __restrict__ edge_col,
    const float* __restrict__ edge_val,
    int* __restrict__ deg,
    int2* __restrict__ ell,
    int n_nodes, int n_edges) {
    __shared__ float sw[IN_F * OUT_F];        // w[k*64 + col]
    __shared__ float sx[64 * 65];             // x rows, padded stride 65

    int t  = threadIdx.x;
    int tx = t & 15;
    int ty = t >> 4;

    // ---- build phase A: edge-row loads in flight early ----
    int chunk = (n_edges + gridDim.x - 1) / gridDim.x;
    int cstart = blockIdx.x * chunk;
    int cend   = cstart + chunk;
    if (cend > n_edges) cend = n_edges;

    int  e[BPT], r[BPT];
    bool ok[BPT];
    #pragma unroll
    for (int i = 0; i < BPT; ++i) {
        e[i]  = cstart + i * 256 + t;
        ok[i] = (e[i] < cend);
        int ee = ok[i] ? e[i] : 0;
        r[i] = __ldg(edge_row + ee);
    }

    // ---- stage W and x (vectorized LDG) ----
    #pragma unroll
    for (int j = 0; j < 4; ++j) {
        int i4 = t + j * 256;                 // float4 index into w
        float4 wv4 = *reinterpret_cast<const float4*>(w + i4 * 4);
        *reinterpret_cast<float4*>(&sw[i4 * 4]) = wv4;
    }

    int base = blockIdx.x * 64;
    #pragma unroll
    for (int j = 0; j < 4; ++j) {
        int i4 = t + j * 256;                 // float4 index into x tile
        int rr = i4 >> 4;
        int kk = (i4 & 15) * 4;
        int node = base + rr;
        float4 xv4 = (node < n_nodes)
            ? *reinterpret_cast<const float4*>(x + (long long)node * IN_F + kk)
            : make_float4(0.f, 0.f, 0.f, 0.f);
        float* dst = &sx[rr * 65 + kk];
        dst[0] = xv4.x; dst[1] = xv4.y; dst[2] = xv4.z; dst[3] = xv4.w;
    }
    __syncthreads();

    // ---- build phase B: atomics + col/val loads (latency hidden below) ----
    int rank[BPT];
    #pragma unroll
    for (int i = 0; i < BPT; ++i)
        rank[i] = ok[i] ? atomicAdd(&deg[r[i]], 1) : ELL_W;

    int   c[BPT];
    float v[BPT];
    #pragma unroll
    for (int i = 0; i < BPT; ++i) {
        int ee = ok[i] ? e[i] : 0;
        c[i] = __ldg(edge_col + ee);
        v[i] = __ldg(edge_val + ee);
    }

    // ---- GEMM compute (covers the atomic/LDG latency above) ----
    float acc[4][4] = {};
    #pragma unroll
    for (int k = 0; k < IN_F; ++k) {
        float xv[4];
        #pragma unroll
        for (int rr = 0; rr < 4; ++rr) xv[rr] = sx[(ty * 4 + rr) * 65 + k];
        float4 wv = *reinterpret_cast<const float4*>(&sw[k * OUT_F + tx * 4]);
        #pragma unroll
        for (int rr = 0; rr < 4; ++rr) {
            acc[rr][0] = fmaf(xv[rr], wv.x, acc[rr][0]);
            acc[rr][1] = fmaf(xv[rr], wv.y, acc[rr][1]);
            acc[rr][2] = fmaf(xv[rr], wv.z, acc[rr][2]);
            acc[rr][3] = fmaf(xv[rr], wv.w, acc[rr][3]);
        }
    }

    #pragma unroll
    for (int rr = 0; rr < 4; ++rr) {
        int node = base + ty * 4 + rr;
        if (node < n_nodes) {
            __half2 h0 = __floats2half2_rn(acc[rr][0], acc[rr][1]);
            __half2 h1 = __floats2half2_rn(acc[rr][2], acc[rr][3]);
            uint2 packed = make_uint2(
                *reinterpret_cast<unsigned*>(&h0),
                *reinterpret_cast<unsigned*>(&h1));
            *reinterpret_cast<uint2*>(suph + (long long)node * OUT_F + tx * 4)
                = packed;
        }
    }

    // ---- build phase C: ELL stores (ranks returned long ago) ----
    #pragma unroll
    for (int i = 0; i < BPT; ++i) {
        if (ok[i] && rank[i] < ELL_W) {
            ell[(long long)r[i] * ELL_W + rank[i]] =
                make_int2(c[i], __float_as_int(v[i]));
        }
    }

    // Fallback (never executes for these sizes: chunk <= 1024)
    for (int ebase = cstart + 256 * BPT; ebase < cend; ebase += 256) {
        int ee = ebase + t;
        if (ee < cend) {
            int rr2 = __ldg(edge_row + ee);
            int rk = atomicAdd(&deg[rr2], 1);
            if (rk < ELL_W)
                ell[(long long)rr2 * ELL_W + rk] =
                    make_int2(__ldg(edge_col + ee),
                              __float_as_int(__ldg(edge_val + ee)));
        }
    }
}

// ---------------------------------------------------------------------------
// Kernel 2: accumulate — EXACT R12 form (proven 17.3us): 16 threads per row,
// lane owns one uint2 (4 halves); fp32 accumulation; predicated batches of 4.
// ---------------------------------------------------------------------------
__global__ __launch_bounds__(256) void accumulate_kernel(
    const int* __restrict__ deg,
    const int2* __restrict__ ell,
    const __half* __restrict__ suph,
    const float* __restrict__ bias,
    float* __restrict__ out,
    int n_nodes) {
    int t = threadIdx.x;
    int g = blockIdx.x * 16 + (t >> 4);
    int l = t & 15;
    if (g >= n_nodes) return;

    int d = deg[g];
    if (d > ELL_W) d = ELL_W;
    const int2* row = ell + (long long)g * ELL_W;

    float4 acc = *reinterpret_cast<const float4*>(bias + l * 4);

    for (int e = 0; e < d; e += 4) {
        int2 ev[4];
        #pragma unroll
        for (int i = 0; i < 4; ++i) ev[i] = __ldg(row + e + i);
        uint2 sh[4];
        #pragma unroll
        for (int i = 0; i < 4; ++i)
            sh[i] = *reinterpret_cast<const uint2*>(
                suph + (long long)ev[i].x * OUT_F + l * 4);
        #pragma unroll
        for (int i = 0; i < 4; ++i) {
            float v = (e + i < d) ? __int_as_float(ev[i].y) : 0.0f;
            float2 f0 = __half22float2(*reinterpret_cast<__half2*>(&sh[i].x));
            float2 f1 = __half22float2(*reinterpret_cast<__half2*>(&sh[i].y));
            acc.x = fmaf(v, f0.x, acc.x);
            acc.y = fmaf(v, f0.y, acc.y);
            acc.z = fmaf(v, f1.x, acc.z);
            acc.w = fmaf(v, f1.y, acc.w);
        }
    }

    *reinterpret_cast<float4*>(out + (long long)g * OUT_F + l * 4) = acc;
}

// ---------------------------------------------------------------------------
// Launch: inputs in order  x, edge_row, edge_col, edge_val, weight, bias
// ---------------------------------------------------------------------------
extern "C" void kernel_launch(void* const* d_in, const int* in_sizes, int n_in,
                              void* d_out, int out_size) {
    const float* x        = (const float*)d_in[0];
    const int*   edge_row = (const int*)  d_in[1];
    const int*   edge_col = (const int*)  d_in[2];
    const float* edge_val = (const float*)d_in[3];
    const float* weight   = (const float*)d_in[4];
    const float* bias     = (const float*)d_in[5];
    float* out = (float*)d_out;

    int n_nodes = in_sizes[0] / IN_F;
    int n_edges = in_sizes[1];

    __half* suph;
    int* deg;
    int2* ell;
    cudaGetSymbolAddress((void**)&suph, g_support_h);
    cudaGetSymbolAddress((void**)&deg,  g_deg);
    cudaGetSymbolAddress((void**)&ell,  g_ell);

    // 0) zero deg (graph memset node)
    cudaMemsetAsync(deg, 0, n_nodes * sizeof(int));

    // 1) fused + pipelined GEMM/ELL build
    int blocks = (n_nodes + 63) / 64;
    gemm_build_kernel<<<blocks, 256>>>(x, weight, suph,
                                       edge_row, edge_col, edge_val,
                                       deg, ell, n_nodes, n_edges);

    // 2) accumulate (16 lanes per row — R12 proven)
    int ablocks = (n_nodes * 16 + 255) / 256;
    accumulate_kernel<<<ablocks, 256>>>(deg, ell, suph, bias, out, n_nodes);
}